// round 9
// baseline (speedup 1.0000x reference)
#include <cuda_runtime.h>
#include <cstdint>

// SimplePatchScorer: out[b, j] = dot(W, permuted_patch_row(b, j)) + bias
//   x: (512, 3, 224, 224) fp32, W: (1,768), b: (1,) -> out: (512, 196)
//
// flat[u], u = s*588 + v; s = ph*16+pw; v = c*196 + hn*14 + wn.
// out[b,j] = sum_t W[t]*flat[768j+t] + bias.
// lcm(588,768)=37632 => 4 groups/image: s in [64g,64g+64), j in [49g,49g+49).
//
// v7: warp-specialized producer/consumer. 512 threads: warps 12-15 stream
// eighth-tiles (8 s' rows = one ph + pw-half; contiguous u' range
// [4704h,4704h+4704)) gmem -> transposed smem via LDG.128 + 4x STS into a
// DOUBLE BUFFER; warps 0-11 run the float4-LDS dot. Named-barrier
// handshake (full=1/2, empty=3/4, count 512). ~41 KB smem -> 2 CTAs/SM.

#define VPAD    604
#define TILE_U  4704           // 8 * 588
#define THREADS 512
#define NCONS   384            // 12 consumer warps

__device__ __forceinline__ void bar_sync_id(int id) {
    asm volatile("bar.sync %0, %1;" :: "r"(id), "r"(THREADS) : "memory");
}
__device__ __forceinline__ void bar_arrive_id(int id) {
    asm volatile("bar.arrive %0, %1;" :: "r"(id), "r"(THREADS) : "memory");
}

__global__ __launch_bounds__(THREADS, 2)
void patch_scorer_v7(const float* __restrict__ x,
                     const float* __restrict__ W,
                     const float* __restrict__ bias,
                     float* __restrict__ out)
{
    extern __shared__ float smem[];
    float* Ws = smem + 16 * VPAD;        // [768] after 2 x [8][604] buffers

    const int tid  = threadIdx.x;
    const int g    = blockIdx.x & 3;
    const int b    = blockIdx.x >> 2;
    const int lane = tid & 31;
    const int warp = tid >> 5;           // 16 warps

    const float* xb = x + (size_t)b * (3 * 224 * 224);

    if (tid < 192)                       // 192 float4 = 768 floats
        ((float4*)Ws)[tid] = ((const float4*)W)[tid];
    __syncthreads();

    if (warp >= 12) {
        // ================= PRODUCERS (warps 12-15, 128 threads) =========
        // Tile h: ph = 4g + h/2, pw-half = h&1. float4 f in [0,1176):
        //   q4 = f%28 (wn = q4>>1, kk = q4&1), r = f/28 (hn = r%14, c = r/14)
        // gmem float idx: c*50176 + (hn*16+ph)*224 + wn*16 + 8*half + 4*kk
        // smem: (4*kk+e)*VPAD + c*196 + hn*14 + wn   (e = elem 0..3)
        const int ptid = tid - NCONS;    // 0..127
        const int q40  = ptid % 28;
        const int r0   = ptid / 28;
        const int hn0  = r0 % 14;
        const int c0   = r0 / 14;

        for (int h = 0; h < 8; h++) {
            if (h >= 2) bar_sync_id(3 + (h & 1));     // wait buffer empty
            float* Y = smem + (h & 1) * (8 * VPAD);
            const int ph = 4 * g + (h >> 1);
            const float* bp = xb + 8 * (h & 1);

            int q4 = q40, hn = hn0, c = c0;
            #pragma unroll
            for (int k = 0; k < 9; k++) {             // f = ptid + 128k
                int wn = q4 >> 1, kk = q4 & 1;
                float4 val = __ldcs((const float4*)(bp + (size_t)c * 50176
                                 + (hn * 16 + ph) * 224 + wn * 16 + 4 * kk));
                float* dst = Y + (kk << 2) * VPAD + c * 196 + hn * 14 + wn;
                dst[0 * VPAD] = val.x;
                dst[1 * VPAD] = val.y;
                dst[2 * VPAD] = val.z;
                dst[3 * VPAD] = val.w;
                // f += 128: q4 += 16 (mod 28), r += 4/5; hn carry into c
                q4 += 16;
                int rinc = 4;
                if (q4 >= 28) { q4 -= 28; rinc = 5; }
                hn += rinc;
                if (hn >= 14) { hn -= 14; c++; }
            }
            if (ptid < 24) {                          // tail f = 1152+ptid
                int wn = (4 + ptid) >> 1, kk = (4 + ptid) & 1;
                float4 val = __ldcs((const float4*)(bp + 2 * 50176
                                 + (13 * 16 + ph) * 224 + wn * 16 + 4 * kk));
                float* dst = Y + (kk << 2) * VPAD + 2 * 196 + 13 * 14 + wn;
                dst[0 * VPAD] = val.x;
                dst[1 * VPAD] = val.y;
                dst[2 * VPAD] = val.z;
                dst[3 * VPAD] = val.w;
            }
            __threadfence_block();                    // STS visible to consumers
            bar_arrive_id(1 + (h & 1));               // signal buffer full
        }
    } else {
        // ================= CONSUMERS (warps 0-11, 384 threads) ==========
        const int cw = warp;                          // 0..11
        float acc[5];
        #pragma unroll
        for (int i = 0; i < 5; i++) acc[i] = 0.f;

        for (int h = 0; h < 8; h++) {
            bar_sync_id(1 + (h & 1));                 // wait buffer full
            const float* Yt = smem + (h & 1) * (8 * VPAD);
            const int rlo = TILE_U * h, rhi = rlo + TILE_U;
            const int sp0 = 8 * h;

            #pragma unroll
            for (int i = 0; i < 5; i++) {
                int jl = cw + 12 * i;                 // warp's rows
                if (jl < 49) {
                    int ulo = max(768 * jl, rlo);
                    int uhi = min(768 * jl + 768, rhi);
                    int u   = ulo + 4 * lane;
                    if (u < uhi) {
                        int sp = (unsigned)u / 588u;  // one div per segment
                        int v  = u - sp * 588;
                        int yo = (sp - sp0) * VPAD + v;
                        int wo = u - 768 * jl;
                        float a = 0.f;
                        while (u < uhi) {
                            float4 yv = *(const float4*)&Yt[yo];
                            float4 wv = *(const float4*)&Ws[wo];
                            a = fmaf(wv.x, yv.x, a);
                            a = fmaf(wv.y, yv.y, a);
                            a = fmaf(wv.z, yv.z, a);
                            a = fmaf(wv.w, yv.w, a);
                            u  += 128;                // 32 lanes * 4 floats
                            wo += 128;
                            v  += 128;
                            yo += 128;
                            if (v >= 588) { v -= 588; yo += VPAD - 588; }
                        }
                        acc[i] += a;
                    }
                }
            }
            if (h + 2 < 8) bar_arrive_id(3 + (h & 1)); // signal buffer empty
        }

        // ---- final warp reductions + store ----
        const float bv = __ldg(bias);
        #pragma unroll
        for (int i = 0; i < 5; i++) {
            int jl = cw + 12 * i;
            if (jl < 49) {
                float a = acc[i];
                #pragma unroll
                for (int off = 16; off; off >>= 1)
                    a += __shfl_xor_sync(0xffffffffu, a, off);
                if (lane == 0)
                    out[b * 196 + 49 * g + jl] = a + bv;
            }
        }
    }
}

extern "C" void kernel_launch(void* const* d_in, const int* in_sizes, int n_in,
                              void* d_out, int out_size)
{
    const float* x  = (const float*)d_in[0];
    const float* W  = (const float*)d_in[1];
    const float* bb = (const float*)d_in[2];
    float* out = (float*)d_out;

    const int smem_bytes = (16 * VPAD + 768) * sizeof(float);  // ~41.8 KB
    cudaFuncSetAttribute(patch_scorer_v7,
                         cudaFuncAttributeMaxDynamicSharedMemorySize, smem_bytes);

    patch_scorer_v7<<<512 * 4, THREADS, smem_bytes>>>(x, W, bb, out);
}

// round 10
// speedup vs baseline: 1.9254x; 1.9254x over previous
#include <cuda_runtime.h>
#include <cstdint>

// SimplePatchScorer: out[b, j] = dot(W, permuted_patch_row(b, j)) + bias
//   x: (512, 3, 224, 224) fp32, W: (1,768), b: (1,) -> out: (512, 196)
//
// flat[u], u = s*588 + v; s = ph*16+pw; v = c*196 + hn*14 + wn.
// out[b,j] = sum_t W[t]*flat[768j+t] + bias.
// lcm(588,768)=37632 => 4 groups/image: s in [64g,64g+64), j in [49g,49g+49).
//
// v8: register-staged software pipeline. Eighth-tiles (8 s' rows = one ph +
// pw-half; contiguous u' range [4704h,4704h+4704)). Every thread stages <=5
// float4 of tile h+1 in registers (LDG.128 issued BEFORE computing tile h,
// so DRAM latency hides under the dot), then drains to the other smem
// buffer. Double buffer -> 1 barrier/tile. Offsets are tile-invariant and
// precomputed once. ~41.7 KB smem, <=64 regs -> 4 CTAs/SM.

#define VPAD    604
#define TILE_U  4704           // 8 * 588
#define THREADS 256

__global__ __launch_bounds__(THREADS, 4)
void patch_scorer_v8(const float* __restrict__ x,
                     const float* __restrict__ W,
                     const float* __restrict__ bias,
                     float* __restrict__ out)
{
    extern __shared__ float smem[];
    float* Ws = smem + 16 * VPAD;        // [768] after 2 x [8][604] buffers

    const int tid  = threadIdx.x;
    const int g    = blockIdx.x & 3;
    const int b    = blockIdx.x >> 2;
    const int lane = tid & 31;
    const int warp = tid >> 5;           // 8 warps

    const float* xb = x + (size_t)b * (3 * 224 * 224);

    if (tid < 192)                       // 192 float4 = 768 floats
        ((float4*)Ws)[tid] = ((const float4*)W)[tid];

    // ---- tile-invariant per-thread load/store offsets (f = tid + 256k) ----
    // f in [0,1176): q4 = f%28 (wn = q4>>1, kk = q4&1), r = f/28
    //   (hn = r%14, c = r/14)
    // gmem (rel, floats): c*50176 + hn*16*224 + wn*16 + 4kk  (+ ph*224 + 8*half)
    // smem (floats):      (4kk)*VPAD + c*196 + hn*14 + wn    (+ e*VPAD)
    int  goff[5], soff[5];
    bool pk[5];
    #pragma unroll
    for (int k = 0; k < 5; k++) {
        int f  = tid + 256 * k;
        pk[k]  = (f < 1176);
        int q4 = f % 28;
        int r  = f / 28;
        int wn = q4 >> 1, kk = q4 & 1;
        int hn = r % 14,  c  = r / 14;
        goff[k] = c * 50176 + hn * 3584 + wn * 16 + 4 * kk;
        soff[k] = (kk << 2) * VPAD + c * 196 + hn * 14 + wn;
    }

    float4 st[5];
    auto issue_loads = [&](int h) {
        const float* bp = xb + (4 * g + (h >> 1)) * 224 + 8 * (h & 1);
        #pragma unroll
        for (int k = 0; k < 5; k++)
            if (pk[k]) st[k] = __ldcs((const float4*)(bp + goff[k]));
    };
    auto drain_stores = [&](float* Y) {
        #pragma unroll
        for (int k = 0; k < 5; k++)
            if (pk[k]) {
                float* d = Y + soff[k];
                d[0 * VPAD] = st[k].x;
                d[1 * VPAD] = st[k].y;
                d[2 * VPAD] = st[k].z;
                d[3 * VPAD] = st[k].w;
            }
    };

    float acc[7];
    #pragma unroll
    for (int i = 0; i < 7; i++) acc[i] = 0.f;

    // ---- prologue: tile 0 ----
    issue_loads(0);
    drain_stores(smem);                  // buffer 0
    __syncthreads();

    for (int h = 0; h < 8; h++) {
        if (h < 7) issue_loads(h + 1);   // LDGs in flight during compute

        // ---- compute tile h from buffer h&1 ----
        const float* Yt = smem + (h & 1) * (8 * VPAD);
        const int rlo = TILE_U * h, rhi = rlo + TILE_U;
        const int sp0 = 8 * h;
        #pragma unroll
        for (int i = 0; i < 7; i++) {
            int jl = warp + 8 * i;
            if (jl < 49) {
                int ulo = max(768 * jl, rlo);
                int uhi = min(768 * jl + 768, rhi);
                int u   = ulo + 4 * lane;
                if (u < uhi) {
                    int sp = (unsigned)u / 588u;       // one div per segment
                    int v  = u - sp * 588;
                    int yo = (sp - sp0) * VPAD + v;
                    int wo = u - 768 * jl;
                    float a = 0.f;
                    while (u < uhi) {
                        float4 yv = *(const float4*)&Yt[yo];
                        float4 wv = *(const float4*)&Ws[wo];
                        a = fmaf(wv.x, yv.x, a);
                        a = fmaf(wv.y, yv.y, a);
                        a = fmaf(wv.z, yv.z, a);
                        a = fmaf(wv.w, yv.w, a);
                        u  += 128;                     // 32 lanes * 4 floats
                        wo += 128;
                        v  += 128;
                        yo += 128;
                        if (v >= 588) { v -= 588; yo += VPAD - 588; }
                    }
                    acc[i] += a;
                }
            }
        }

        if (h < 7) {
            drain_stores(smem + ((h + 1) & 1) * (8 * VPAD));
            __syncthreads();             // stores visible; prev reads done
        }
    }

    // ---- final warp reductions + store ----
    const float bv = __ldg(bias);
    #pragma unroll
    for (int i = 0; i < 7; i++) {
        int jl = warp + 8 * i;
        if (jl < 49) {
            float a = acc[i];
            #pragma unroll
            for (int off = 16; off; off >>= 1)
                a += __shfl_xor_sync(0xffffffffu, a, off);
            if (lane == 0)
                out[b * 196 + 49 * g + jl] = a + bv;
        }
    }
}

extern "C" void kernel_launch(void* const* d_in, const int* in_sizes, int n_in,
                              void* d_out, int out_size)
{
    const float* x  = (const float*)d_in[0];
    const float* W  = (const float*)d_in[1];
    const float* bb = (const float*)d_in[2];
    float* out = (float*)d_out;

    const int smem_bytes = (16 * VPAD + 768) * sizeof(float);  // ~41.7 KB
    cudaFuncSetAttribute(patch_scorer_v8,
                         cudaFuncAttributeMaxDynamicSharedMemorySize, smem_bytes);

    patch_scorer_v8<<<512 * 4, THREADS, smem_bytes>>>(x, W, bb, out);
}

// round 11
// speedup vs baseline: 2.0483x; 1.0638x over previous
#include <cuda_runtime.h>
#include <cstdint>

// SimplePatchScorer: out[b, j] = dot(W, permuted_patch_row(b, j)) + bias
//   x: (512, 3, 224, 224) fp32, W: (1,768), b: (1,) -> out: (512, 196)
//
// flat[u], u = s*588 + v; s = ph*16+pw; v = c*196 + hn*14 + wn.
// out[b,j] = sum_t W[t]*flat[768j+t] + bias.
// lcm(588,768)=37632 => 4 groups/image: s in [64g,64g+64), j in [49g,49g+49).
//
// v9 = v5 skeleton (quarter tiles of 16 s' rows, 256 thr, 5 CTAs/SM) plus:
//  - per-CTA quarter-order STAGGER (q0 = (bid>>2)&3) so co-resident CTAs
//    decorrelate their LDG vs LDS phases (DRAM duty cycle up),
//  - XOR swizzle (16B granule ^= row>>2) killing phase-1 STS bank conflicts
//    while keeping phase-2 float4 reads contiguous & conflict-free,
//  - packed fma.rn.f32x2 + ld.shared.v2.b64 in phase 2 (2 FMA / 4 elems).

#define VPAD      604          // mult of 4; 151 granules per row
#define QUARTER_U 9408         // 16 * 588
#define THREADS   256

__global__ __launch_bounds__(THREADS, 5)
void patch_scorer_v9(const float* __restrict__ x,
                     const float* __restrict__ W,
                     const float* __restrict__ bias,
                     float* __restrict__ out)
{
    extern __shared__ float smem[];
    float* Y  = smem;               // [16][604], XOR-swizzled granules
    float* Ws = smem + 16 * VPAD;   // [768]

    const int tid  = threadIdx.x;
    const int g    = blockIdx.x & 3;
    const int b    = blockIdx.x >> 2;
    const int lane = tid & 31;
    const int warp = tid >> 5;      // 8 warps

    const float* xb = x + (size_t)b * 150528;
    const uint32_t ybase = (uint32_t)__cvta_generic_to_shared(Y);
    const uint32_t wbase = (uint32_t)__cvta_generic_to_shared(Ws);

    if (tid < 192)                  // 192 float4 = 768 floats
        ((float4*)Ws)[tid] = ((const float4*)W)[tid];
    // visible after the first phase-1 __syncthreads

    float acc[7];
    #pragma unroll
    for (int i = 0; i < 7; i++) acc[i] = 0.f;

    const int q0 = (blockIdx.x >> 2) & 3;   // stagger start quarter

    for (int qq = 0; qq < 4; qq++) {
        const int q = (q0 + qq) & 3;
        if (qq) __syncthreads();    // protect Y before overwrite

        // ---- Phase 1: stream quarter q's region -> swizzled smem tile ----
        // ph = 4g + q; 42 rows x 56 float4 = 2352 float4 over 256 threads.
        {
            const int hoff = 4 * g + q;
            int w4 = tid % 56;
            int r  = tid / 56;
            int hn = r % 14;
            int c  = r / 14;
            #pragma unroll 2
            for (int e4 = tid; e4 < 2352; e4 += THREADS) {
                int w = w4 << 2;
                float4 val = __ldcs((const float4*)(xb +
                    (size_t)c * 50176 + (hn * 16 + hoff) * 224 + w));

                int pw  = w & 15;               // 0,4,8,12
                int wn  = w >> 4;
                int col = c * 196 + hn * 14 + wn;
                // swizzled column: granule ^ (row>>2); row>>2 == pw>>2 for e=0..3
                int xcol = ((((col >> 2) ^ (pw >> 2)) << 2)) | (col & 3);
                float* dst = Y + pw * VPAD + xcol;
                dst[0 * VPAD] = val.x;
                dst[1 * VPAD] = val.y;
                dst[2 * VPAD] = val.z;
                dst[3 * VPAD] = val.w;

                w4 += 32;                       // e4 += 256 carry chain
                int rinc = 4;
                if (w4 >= 56) { w4 -= 56; rinc = 5; }
                hn += rinc;
                if (hn >= 14) { hn -= 14; c++; }
            }
        }
        __syncthreads();

        // ---- Phase 2: packed-f32x2 dot over u' in [9408q, 9408q+9408) ----
        const int rlo = QUARTER_U * q, rhi = rlo + QUARTER_U;
        #pragma unroll
        for (int i = 0; i < 7; i++) {
            int jl = warp + 8 * i;
            if (jl < 49) {
                int ulo = max(768 * jl, rlo);
                int uhi = min(768 * jl + 768, rhi);
                int u   = ulo + 4 * lane;
                if (u < uhi) {
                    int sp = (unsigned)u / 588u;          // one div per segment
                    int v  = u - sp * 588;
                    int rl = sp - 16 * q;                 // local row 0..15
                    uint32_t ya = ybase + 4u * (rl * VPAD
                                 + ((((v >> 2) ^ (rl >> 2)) << 2)));
                    uint32_t wa = wbase + 4u * (u - 768 * jl);
                    unsigned long long p01 = 0, p23 = 0;
                    while (u < uhi) {
                        unsigned long long y01, y23, w01, w23;
                        asm volatile("ld.shared.v2.b64 {%0,%1}, [%2];"
                                     : "=l"(y01), "=l"(y23) : "r"(ya));
                        asm volatile("ld.shared.v2.b64 {%0,%1}, [%2];"
                                     : "=l"(w01), "=l"(w23) : "r"(wa));
                        asm volatile("fma.rn.f32x2 %0, %1, %2, %0;"
                                     : "+l"(p01) : "l"(y01), "l"(w01));
                        asm volatile("fma.rn.f32x2 %0, %1, %2, %0;"
                                     : "+l"(p23) : "l"(y23), "l"(w23));
                        u  += 128;            // 32 lanes * 4 floats
                        wa += 512;
                        v  += 128;
                        if (v >= 588) {       // row wrap: re-derive swizzled addr
                            v -= 588; rl++;
                            ya = ybase + 4u * (rl * VPAD
                                 + ((((v >> 2) ^ (rl >> 2)) << 2)));
                        } else {
                            ya += 512;        // +32 granules; XOR bits (0-1) safe
                        }
                    }
                    acc[i] += (__uint_as_float((uint32_t)p01)
                             + __uint_as_float((uint32_t)(p01 >> 32)))
                            + (__uint_as_float((uint32_t)p23)
                             + __uint_as_float((uint32_t)(p23 >> 32)));
                }
            }
        }
    }

    // ---- final warp reductions + store ----
    const float bv = __ldg(bias);
    #pragma unroll
    for (int i = 0; i < 7; i++) {
        int jl = warp + 8 * i;
        if (jl < 49) {
            float a = acc[i];
            #pragma unroll
            for (int off = 16; off; off >>= 1)
                a += __shfl_xor_sync(0xffffffffu, a, off);
            if (lane == 0)
                out[b * 196 + 49 * g + jl] = a + bv;
        }
    }
}

extern "C" void kernel_launch(void* const* d_in, const int* in_sizes, int n_in,
                              void* d_out, int out_size)
{
    const float* x  = (const float*)d_in[0];
    const float* W  = (const float*)d_in[1];
    const float* bb = (const float*)d_in[2];
    float* out = (float*)d_out;

    const int smem_bytes = (16 * VPAD + 768) * sizeof(float);  // ~40.8 KB
    cudaFuncSetAttribute(patch_scorer_v9,
                         cudaFuncAttributeMaxDynamicSharedMemorySize, smem_bytes);

    patch_scorer_v9<<<512 * 4, THREADS, smem_bytes>>>(x, W, bb, out);
}